// round 3
// baseline (speedup 1.0000x reference)
#include <cuda_runtime.h>

#define BATCH 16
#define NPTS 4096
#define NPT 1024
#define KNB 32
#define R2C 0.04f

// ---------------- scratch (device globals; no allocation allowed) ----------
__device__ float g_P1[BATCH * NPTS * 64];     // points @ w0[:64] + b0
__device__ float g_xyzT[BATCH * 3 * NPTS];    // xyz transposed per batch
__device__ int   g_ball[BATCH * NPT * KNB];   // ball-query indices

// ---------------- kernel 1: transpose xyz to SoA ---------------------------
__global__ void transpose_xyz(const float* __restrict__ xyz) {
    int i = blockIdx.x * blockDim.x + threadIdx.x;
    if (i >= BATCH * NPTS) return;
    int b = i / NPTS, n = i % NPTS;
    float x = xyz[(size_t)i * 3 + 0];
    float y = xyz[(size_t)i * 3 + 1];
    float z = xyz[(size_t)i * 3 + 2];
    g_xyzT[b * 3 * NPTS + 0 * NPTS + n] = x;
    g_xyzT[b * 3 * NPTS + 1 * NPTS + n] = y;
    g_xyzT[b * 3 * NPTS + 2 * NPTS + n] = z;
}

// ---------------- kernel 2: farthest point sampling ------------------------
// One block per batch. 512 threads, 8 points per thread, dist in registers,
// coords in shared. Output: new_xyz written directly to d_out region 0.
__global__ __launch_bounds__(512) void fps_kernel(const float* __restrict__ xyz,
                                                  float* __restrict__ newxyz) {
    extern __shared__ float sm[];
    float* shx = sm;
    float* shy = sm + NPTS;
    float* shz = sm + 2 * NPTS;
    float* wval = sm + 3 * NPTS;          // 16 warp maxima
    int*   widx = (int*)(sm + 3 * NPTS + 16);
    int*   sfar = (int*)(sm + 3 * NPTS + 32);

    int tid = threadIdx.x;
    int b = blockIdx.x;
    const float* xb = xyz + (size_t)b * NPTS * 3;
    for (int i = tid; i < NPTS; i += 512) {
        shx[i] = xb[i * 3 + 0];
        shy[i] = xb[i * 3 + 1];
        shz[i] = xb[i * 3 + 2];
    }
    __syncthreads();

    float lx[8], ly[8], lz[8], ld[8];
#pragma unroll
    for (int j = 0; j < 8; j++) {
        int p = tid + j * 512;
        lx[j] = shx[p]; ly[j] = shy[p]; lz[j] = shz[p];
        ld[j] = 1e10f;
    }

    int far = 0;
    float* outb = newxyz + (size_t)b * NPT * 3;
#pragma unroll 1
    for (int it = 0; it < NPT; it++) {
        float cx = shx[far], cy = shy[far], cz = shz[far];
        if (tid == 0) {
            outb[it * 3 + 0] = cx;
            outb[it * 3 + 1] = cy;
            outb[it * 3 + 2] = cz;
        }
        float bv = -1.0f; int bi = 0;
#pragma unroll
        for (int j = 0; j < 8; j++) {
            int p = tid + j * 512;
            float dx = lx[j] - cx, dy = ly[j] - cy, dz = lz[j] - cz;
            float d = dx * dx + dy * dy + dz * dz;
            float nd = fminf(ld[j], d);
            ld[j] = nd;
            if (nd > bv) { bv = nd; bi = p; }   // p strictly increasing -> lowest-idx tie
        }
#pragma unroll
        for (int off = 16; off > 0; off >>= 1) {
            float ov = __shfl_down_sync(0xffffffffu, bv, off);
            int   oi = __shfl_down_sync(0xffffffffu, bi, off);
            if (ov > bv || (ov == bv && oi < bi)) { bv = ov; bi = oi; }
        }
        if ((tid & 31) == 0) { wval[tid >> 5] = bv; widx[tid >> 5] = bi; }
        __syncthreads();
        if (tid < 16) {
            bv = wval[tid]; bi = widx[tid];
#pragma unroll
            for (int off = 8; off > 0; off >>= 1) {
                float ov = __shfl_down_sync(0xffffu, bv, off, 16);
                int   oi = __shfl_down_sync(0xffffu, bi, off, 16);
                if (ov > bv || (ov == bv && oi < bi)) { bv = ov; bi = oi; }
            }
            if (tid == 0) *sfar = bi;
        }
        __syncthreads();
        far = *sfar;
    }
}

// ---------------- kernel 3: P1 = points @ w0[:64] + b0 ---------------------
// One row per thread, weights in shared.
__global__ __launch_bounds__(256) void p1_kernel(const float* __restrict__ points,
                                                 const float* __restrict__ w0,
                                                 const float* __restrict__ b0) {
    __shared__ float sw[64 * 64];
    __shared__ float sb[64];
    int tid = threadIdx.x;
    for (int i = tid; i < 4096; i += 256) sw[i] = w0[i];
    if (tid < 64) sb[tid] = b0[tid];
    __syncthreads();

    int row = blockIdx.x * 256 + tid;           // b*4096 + n
    const float* x = points + (size_t)row * 64;
    float acc[64];
#pragma unroll
    for (int f = 0; f < 64; f++) acc[f] = sb[f];

#pragma unroll 2
    for (int c4 = 0; c4 < 16; c4++) {
        float4 xv = *(const float4*)(x + c4 * 4);
        float xs[4] = {xv.x, xv.y, xv.z, xv.w};
#pragma unroll
        for (int u = 0; u < 4; u++) {
            int c = c4 * 4 + u;
#pragma unroll
            for (int f4 = 0; f4 < 16; f4++) {
                float4 wv = *(const float4*)&sw[c * 64 + f4 * 4];
                acc[f4 * 4 + 0] += xs[u] * wv.x;
                acc[f4 * 4 + 1] += xs[u] * wv.y;
                acc[f4 * 4 + 2] += xs[u] * wv.z;
                acc[f4 * 4 + 3] += xs[u] * wv.w;
            }
        }
    }
    float* o = g_P1 + (size_t)row * 64;
#pragma unroll
    for (int f4 = 0; f4 < 16; f4++)
        *(float4*)(o + f4 * 4) =
            make_float4(acc[f4 * 4 + 0], acc[f4 * 4 + 1], acc[f4 * 4 + 2], acc[f4 * 4 + 3]);
}

// ---------------- kernel 4: ball query (one warp per centroid) -------------
__global__ __launch_bounds__(256) void query_kernel(const float* __restrict__ newxyz) {
    int gw = (blockIdx.x * 256 + threadIdx.x) >> 5;   // centroid id = b*1024+s
    int lane = threadIdx.x & 31;
    int b = gw >> 10;
    float cx = newxyz[(size_t)gw * 3 + 0];
    float cy = newxyz[(size_t)gw * 3 + 1];
    float cz = newxyz[(size_t)gw * 3 + 2];
    const float* xb = g_xyzT + b * 3 * NPTS;
    int* outp = g_ball + (size_t)gw * KNB;

    int cnt = 0, first = 0;
    bool havefirst = false;
    for (int ch = 0; ch < NPTS / 32; ch++) {
        int n = ch * 32 + lane;
        float dx = xb[n] - cx, dy = xb[NPTS + n] - cy, dz = xb[2 * NPTS + n] - cz;
        float d2 = dx * dx + dy * dy + dz * dz;
        unsigned m = __ballot_sync(0xffffffffu, d2 <= R2C);
        if (m) {
            if (!havefirst) { first = ch * 32 + __ffs(m) - 1; havefirst = true; }
            int pos = cnt + __popc(m & ((1u << lane) - 1u));
            if (((m >> lane) & 1u) && pos < KNB) outp[pos] = n;
            cnt += __popc(m);
            if (cnt >= KNB) break;   // cnt warp-uniform
        }
    }
    if (cnt < KNB && lane >= cnt) outp[lane] = first;   // pad with first match
}

// ---------------- kernel 5: fused grouping + MLP + maxpool -----------------
// Block = 256 threads = 2 groups x 128; each group sequentially processes 2
// centroids (4 per block). Weights staged in shared; h buffer stored
// transposed [c][k] and reused between layers; register tiles 4kx4f / 4kx8f.
__global__ __launch_bounds__(256, 2) void mlp_kernel(
    const float* __restrict__ xyz, const float* __restrict__ w0,
    const float* __restrict__ b1, const float* __restrict__ w1,
    const float* __restrict__ w2, const float* __restrict__ b2,
    const float* __restrict__ newxyz, float* __restrict__ newpts) {
    extern __shared__ char smraw[];
    float* w1s   = (float*)smraw;            // 4096 f (16384 B)
    float* w2s   = w1s + 4096;               // 8192 f
    float* w0t   = w2s + 8192;               // 192 f (xyz rows of w0)
    float* b1s   = w0t + 192;                // 64
    float* b2s   = b1s + 64;                 // 128
    float* hbuf  = b2s + 128;                // 2 * 2048 (h transposed [c][k])
    float* dxyzs = hbuf + 2 * 2048;          // 2 * 96
    int*   sidx  = (int*)(dxyzs + 2 * 96);   // 2 * 32
    float* pmax  = (float*)(sidx + 2 * 32);  // 2 * 8*128

    int tid = threadIdx.x;
    for (int i = tid; i < 4096; i += 256) w1s[i] = w1[i];
    for (int i = tid; i < 8192; i += 256) w2s[i] = w2[i];
    if (tid < 192) w0t[tid] = w0[4096 + tid];   // rows 64..66 of [67,64]
    if (tid < 64)  b1s[tid] = b1[tid];
    if (tid < 128) b2s[tid] = b2[tid];
    __syncthreads();

    int g  = tid >> 7;
    int gt = tid & 127;
    float* hb  = hbuf + g * 2048;
    float* dx3 = dxyzs + g * 96;
    int*   sid = sidx + g * 32;
    float* pm  = pmax + g * 1024;
    int kt = gt & 7, ft = gt >> 3;
    int k0 = kt * 4, f0 = ft * 4, f2 = ft * 8;

    for (int itc = 0; itc < 2; itc++) {
        int cid = blockIdx.x * 4 + g * 2 + itc;
        int b = cid >> 10;

        // stage A: gather indices and relative coords
        if (gt < 32) {
            int k = gt;
            int pi = g_ball[(size_t)cid * 32 + k];
            sid[k] = pi;
            const float* pp = xyz + ((size_t)b * NPTS + pi) * 3;
            dx3[k]      = pp[0] - newxyz[(size_t)cid * 3 + 0];
            dx3[32 + k] = pp[1] - newxyz[(size_t)cid * 3 + 1];
            dx3[64 + k] = pp[2] - newxyz[(size_t)cid * 3 + 2];
        }
        __syncthreads();

        // layer 0: relu(P1[idx] + dxyz @ w0[64:67]) -> hb transposed [f][k]
#pragma unroll
        for (int kk = 0; kk < 4; kk++) {
            int k = k0 + kk;
            const float4 p = *(const float4*)(g_P1 + ((size_t)b * NPTS + sid[k]) * 64 + f0);
            float dx = dx3[k], dy = dx3[32 + k], dz = dx3[64 + k];
            float v;
            v = p.x + dx * w0t[f0 + 0] + dy * w0t[64 + f0 + 0] + dz * w0t[128 + f0 + 0];
            hb[(f0 + 0) * 32 + k] = fmaxf(v, 0.f);
            v = p.y + dx * w0t[f0 + 1] + dy * w0t[64 + f0 + 1] + dz * w0t[128 + f0 + 1];
            hb[(f0 + 1) * 32 + k] = fmaxf(v, 0.f);
            v = p.z + dx * w0t[f0 + 2] + dy * w0t[64 + f0 + 2] + dz * w0t[128 + f0 + 2];
            hb[(f0 + 2) * 32 + k] = fmaxf(v, 0.f);
            v = p.w + dx * w0t[f0 + 3] + dy * w0t[64 + f0 + 3] + dz * w0t[128 + f0 + 3];
            hb[(f0 + 3) * 32 + k] = fmaxf(v, 0.f);
        }
        __syncthreads();

        // layer 1: h1 = relu(h0 @ w1 + b1), 4k x 4f register tile
        float a[4][4];
#pragma unroll
        for (int j = 0; j < 4; j++) {
            float bb = b1s[f0 + j];
            a[0][j] = bb; a[1][j] = bb; a[2][j] = bb; a[3][j] = bb;
        }
#pragma unroll 8
        for (int c = 0; c < 64; c++) {
            float4 hv = *(const float4*)&hb[c * 32 + k0];
            float4 wv = *(const float4*)&w1s[c * 64 + f0];
            a[0][0] += hv.x * wv.x; a[0][1] += hv.x * wv.y; a[0][2] += hv.x * wv.z; a[0][3] += hv.x * wv.w;
            a[1][0] += hv.y * wv.x; a[1][1] += hv.y * wv.y; a[1][2] += hv.y * wv.z; a[1][3] += hv.y * wv.w;
            a[2][0] += hv.z * wv.x; a[2][1] += hv.z * wv.y; a[2][2] += hv.z * wv.z; a[2][3] += hv.z * wv.w;
            a[3][0] += hv.w * wv.x; a[3][1] += hv.w * wv.y; a[3][2] += hv.w * wv.z; a[3][3] += hv.w * wv.w;
        }
        __syncthreads();   // all reads of h0 done before overwrite
#pragma unroll
        for (int j = 0; j < 4; j++) {
            float4 o = make_float4(fmaxf(a[0][j], 0.f), fmaxf(a[1][j], 0.f),
                                   fmaxf(a[2][j], 0.f), fmaxf(a[3][j], 0.f));
            *(float4*)&hb[(f0 + j) * 32 + k0] = o;
        }
        __syncthreads();

        // layer 2 + partial max: 4k x 8f register tile
        float a2[4][8];
#pragma unroll
        for (int k = 0; k < 4; k++)
#pragma unroll
            for (int j = 0; j < 8; j++) a2[k][j] = 0.f;
#pragma unroll 4
        for (int c = 0; c < 64; c++) {
            float4 hv = *(const float4*)&hb[c * 32 + k0];
            float4 wa = *(const float4*)&w2s[c * 128 + f2];
            float4 wb = *(const float4*)&w2s[c * 128 + f2 + 4];
            float hvv[4] = {hv.x, hv.y, hv.z, hv.w};
            float wvv[8] = {wa.x, wa.y, wa.z, wa.w, wb.x, wb.y, wb.z, wb.w};
#pragma unroll
            for (int k = 0; k < 4; k++)
#pragma unroll
                for (int j = 0; j < 8; j++) a2[k][j] += hvv[k] * wvv[j];
        }
#pragma unroll
        for (int j = 0; j < 8; j++) {
            float bb = b2s[f2 + j];
            float m = fmaxf(a2[0][j] + bb, 0.f);
            m = fmaxf(m, fmaxf(a2[1][j] + bb, 0.f));
            m = fmaxf(m, fmaxf(a2[2][j] + bb, 0.f));
            m = fmaxf(m, fmaxf(a2[3][j] + bb, 0.f));
            pm[kt * 128 + f2 + j] = m;
        }
        __syncthreads();
        if (gt < 128) {
            float m = pm[gt];
#pragma unroll
            for (int q = 1; q < 8; q++) m = fmaxf(m, pm[q * 128 + gt]);
            newpts[(size_t)cid * 128 + gt] = m;
        }
        __syncthreads();   // protect hb/dx3/pm reuse next iteration
    }
}

// ---------------- launch ----------------------------------------------------
extern "C" void kernel_launch(void* const* d_in, const int* in_sizes, int n_in,
                              void* d_out, int out_size) {
    const float* xyz    = (const float*)d_in[0];
    const float* points = (const float*)d_in[1];
    const float* w0     = (const float*)d_in[2];
    const float* b0     = (const float*)d_in[3];
    const float* w1     = (const float*)d_in[4];
    const float* b1     = (const float*)d_in[5];
    const float* w2     = (const float*)d_in[6];
    const float* b2     = (const float*)d_in[7];

    float* newxyz = (float*)d_out;                       // [16,1024,3]
    float* newpts = newxyz + (size_t)BATCH * NPT * 3;    // [16,1024,128]

    cudaFuncSetAttribute(fps_kernel, cudaFuncAttributeMaxDynamicSharedMemorySize, 49408);
    cudaFuncSetAttribute(mlp_kernel, cudaFuncAttributeMaxDynamicSharedMemorySize, 76288);

    transpose_xyz<<<(BATCH * NPTS + 255) / 256, 256>>>(xyz);
    fps_kernel<<<BATCH, 512, 49408>>>(xyz, newxyz);
    p1_kernel<<<BATCH * NPTS / 256, 256>>>(points, w0, b0);
    query_kernel<<<BATCH * NPT / 8, 256>>>(newxyz);
    mlp_kernel<<<BATCH * NPT / 4, 256, 76288>>>(xyz, w0, b1, w1, w2, b2, newxyz, newpts);
}